// round 5
// baseline (speedup 1.0000x reference)
#include <cuda_runtime.h>
#include <cuda_bf16.h>

// SemiLoss focal loss (gamma=6), single fused kernel.
// Strategy: instead of a scattered gather of logits[n, tgt, p], read ALL K
// class planes with perfectly coalesced float4 loads and select the target
// class with predicated FSELs. ~46MB coalesced beats ~44MB scattered:
// 5.5x fewer L1tex wavefronts, no seg->load dependency, MLP ~22.
//
//   logits : [N, K, P] f32
//   seg    : [N, P]    int64 or int32 (runtime-sniffed)
//   label  : [N]       same int dtype
//   loss = -sum_{n: label[n]!=0} sum_p (1-exp(lp))^6 * lp / count(label!=0)
//   out  = [loss, 0, loss, 0, ...]
//
// Work compaction: blockIdx.x = q*chunksPerRow + chunk where q indexes the
// q-th ACTIVE row; blocks past cnt*chunksPerRow have no plane work. Low
// block indices do the work -> RR scheduler spreads them evenly over SMs.
//
// Completion: atomicAdd(g_total) + threadfence + atomicInc(g_done) wrapping
// at totalBlocks (self-resetting); last block finalizes and resets g_total.

#define CHUNK_PX  2048          // 256 threads * 8 px
#define MAXROWS   1024

__device__ double       g_total = 0.0;
__device__ unsigned int g_done  = 0u;

__device__ __forceinline__ float focal_term(float lp)
{
    float pt = expf(lp);
    float u  = 1.0f - pt;
    float u2 = u * u;
    return u2 * u2 * u2 * lp;   // positive form; negated at the end
}

template<int KK>   // KK > 0: compile-time class count; KK == 0: runtime K
__global__ __launch_bounds__(256)
void semiloss_fused(const float* __restrict__ logits,
                    const void*  __restrict__ seg,
                    const void*  __restrict__ label,
                    int N, int Krt, int P, int chunksPerRow,
                    unsigned int totalBlocks,
                    float* __restrict__ out, int out_size)
{
    const int K   = (KK > 0) ? KK : Krt;
    const int tid = threadIdx.x;

    // ---- dtype sniff: int64 (LE) => every odd 32-bit word of seg is 0 ----
    __shared__ int s_is64;
    if (tid < 32) {
        const int* w = (const int*)seg;
        unsigned b = __ballot_sync(0xffffffffu, w[2 * tid + 1] == 0);
        if (tid == 0) s_is64 = (b == 0xffffffffu) ? 1 : 0;
    }
    __syncthreads();
    const int is64 = s_is64;

    // ---- resolve active row for this block ----
    __shared__ unsigned char s_act[MAXROWS];
    __shared__ int s_row, s_cnt;
    for (int i = tid; i < N; i += blockDim.x) {
        long long lv;
        if (is64) lv = ((const long long*)label)[i];
        else      lv = (long long)((const int*)label)[i];
        s_act[i] = (lv != 0) ? 1 : 0;
    }
    __syncthreads();
    if (tid == 0) {
        int q = blockIdx.x / chunksPerRow;
        int cnt = 0, row = -1;
        for (int i = 0; i < N; ++i) {
            if (s_act[i]) { if (cnt == q) row = i; ++cnt; }
        }
        s_row = row;
        s_cnt = cnt;
    }
    __syncthreads();
    const int row = s_row;

    // ---- read-all + select, 8 pixels per thread (two float4 groups) ----
    double acc = 0.0;
    if (row >= 0) {
        const int chunk = blockIdx.x % chunksPerRow;
        const int pA = chunk * CHUNK_PX + 4 * tid;          // group A
        const int pB = pA + 1024;                           // group B
        const float* base = logits + (size_t)row * (size_t)K * (size_t)P;

        if (pB + 4 <= P) {
            // target classes for the 8 pixels
            int ca[4], cb[4];
            if (is64) {
                const long long* s = (const long long*)seg + (size_t)row * P;
                const longlong2* sa = (const longlong2*)(s + pA);
                const longlong2* sb = (const longlong2*)(s + pB);
                longlong2 a0 = sa[0], a1 = sa[1], b0 = sb[0], b1 = sb[1];
                ca[0] = (int)a0.x; ca[1] = (int)a0.y; ca[2] = (int)a1.x; ca[3] = (int)a1.y;
                cb[0] = (int)b0.x; cb[1] = (int)b0.y; cb[2] = (int)b1.x; cb[3] = (int)b1.y;
            } else {
                const int* s = (const int*)seg + (size_t)row * P;
                int4 a = *(const int4*)(s + pA);
                int4 b = *(const int4*)(s + pB);
                ca[0] = a.x; ca[1] = a.y; ca[2] = a.z; ca[3] = a.w;
                cb[0] = b.x; cb[1] = b.y; cb[2] = b.z; cb[3] = b.w;
            }

            float va[4] = {0.f, 0.f, 0.f, 0.f};
            float vb[4] = {0.f, 0.f, 0.f, 0.f};
            #pragma unroll
            for (int k = 0; k < K; ++k) {
                const float4 ta = *(const float4*)(base + (size_t)k * P + pA);
                const float4 tb = *(const float4*)(base + (size_t)k * P + pB);
                va[0] = (ca[0] == k) ? ta.x : va[0];
                va[1] = (ca[1] == k) ? ta.y : va[1];
                va[2] = (ca[2] == k) ? ta.z : va[2];
                va[3] = (ca[3] == k) ? ta.w : va[3];
                vb[0] = (cb[0] == k) ? tb.x : vb[0];
                vb[1] = (cb[1] == k) ? tb.y : vb[1];
                vb[2] = (cb[2] == k) ? tb.z : vb[2];
                vb[3] = (cb[3] == k) ? tb.w : vb[3];
            }
            #pragma unroll
            for (int i = 0; i < 4; ++i) {
                acc += (double)focal_term(va[i]);
                acc += (double)focal_term(vb[i]);
            }
        } else {
            // tail: scalar gather fallback
            int pEnd = chunk * CHUNK_PX + CHUNK_PX;
            if (pEnd > P) pEnd = P;
            for (int p = chunk * CHUNK_PX + tid; p < pEnd; p += blockDim.x) {
                int cc;
                if (is64) cc = (int)((const long long*)seg)[(size_t)row * P + p];
                else      cc = ((const int*)seg)[(size_t)row * P + p];
                acc += (double)focal_term(__ldg(base + (size_t)cc * P + p));
            }
        }
    }

    // ---- block reduction (double) ----
    for (int off = 16; off > 0; off >>= 1)
        acc += __shfl_down_sync(0xffffffffu, acc, off);
    __shared__ double s_part[8];
    const int lane = tid & 31, wid = tid >> 5;
    if (lane == 0) s_part[wid] = acc;
    __syncthreads();

    __shared__ int s_islast;
    if (tid == 0) {
        double v = 0.0;
        #pragma unroll
        for (int w = 0; w < 8; ++w) v += s_part[w];
        if (v != 0.0) atomicAdd(&g_total, v);
        __threadfence();
        unsigned old = atomicInc(&g_done, totalBlocks - 1u);
        s_islast = (old == totalBlocks - 1u) ? 1 : 0;
    }
    __syncthreads();

    // ---- last block: finalize ----
    if (s_islast) {
        __shared__ float s_loss;
        if (tid == 0) {
            double tot = *((volatile double*)&g_total);
            s_loss = (float)(-tot / (double)s_cnt);
            g_total = 0.0;          // reset for next graph replay
            __threadfence();
        }
        __syncthreads();
        float loss = s_loss;
        for (int i = tid; i < out_size; i += blockDim.x)
            out[i] = (i == 0 || i == 2) ? loss : 0.0f;
    }
}

extern "C" void kernel_launch(void* const* d_in, const int* in_sizes, int n_in,
                              void* d_out, int out_size)
{
    const float* logits = (const float*)d_in[0];
    const void*  seg    = d_in[1];
    const void*  label  = d_in[2];

    int N = in_sizes[2];                 // B*S
    int P = in_sizes[1] / N;             // H*W
    int K = in_sizes[0] / in_sizes[1];   // classes

    const int THREADS = 256;
    int chunksPerRow = (P + CHUNK_PX - 1) / CHUNK_PX;
    unsigned int totalBlocks = (unsigned int)N * (unsigned int)chunksPerRow;

    if (K == 11) {
        semiloss_fused<11><<<totalBlocks, THREADS>>>(logits, seg, label,
                                                     N, K, P, chunksPerRow,
                                                     totalBlocks,
                                                     (float*)d_out, out_size);
    } else {
        semiloss_fused<0><<<totalBlocks, THREADS>>>(logits, seg, label,
                                                    N, K, P, chunksPerRow,
                                                    totalBlocks,
                                                    (float*)d_out, out_size);
    }
}

// round 6
// speedup vs baseline: 1.1117x; 1.1117x over previous
#include <cuda_runtime.h>
#include <cuda_bf16.h>

// SemiLoss focal loss (gamma=6), single fused kernel, perfectly balanced.
//   logits : [N, K, P] f32
//   seg    : [N, P]    int64 or int32 (runtime-sniffed)
//   label  : [N]       same int dtype
//   loss = -sum_{n: label[n]!=0} sum_p (1-exp(lp))^6 * lp / count(label!=0)
//   out  = [loss, 0, loss, 0, ...]
//
// Work model: active work = cnt * P pixels, split into UNIT_PX=1024 pixel
// units (cnt * unitsPerRow total). Every block grid-strides over units, so
// all launched blocks work regardless of which rows are active. The active
// ordinal -> row map is built in O(1) with ballots (no serial scan).
//
// Completion: atomicAdd(g_total) + threadfence + atomicInc(g_done) wrapping
// at gridDim.x (self-resetting); last block finalizes out and resets g_total
// so the kernel is deterministic across CUDA-graph replays.

#define UNIT_PX   1024          // 256 threads * 4 px
#define MAXROWS   256           // N <= 256 supported by the ballot mapper

__device__ double       g_total = 0.0;
__device__ unsigned int g_done  = 0u;

__device__ __forceinline__ float focal_term(float lp)
{
    float pt = expf(lp);
    float u  = 1.0f - pt;
    float u2 = u * u;
    return u2 * u2 * u2 * lp;   // positive form; negated at the end
}

__global__ __launch_bounds__(256)
void semiloss_fused(const float* __restrict__ logits,
                    const void*  __restrict__ seg,
                    const void*  __restrict__ label,
                    int N, int K, int P, int unitsPerRow,
                    float* __restrict__ out, int out_size)
{
    const int tid = threadIdx.x;

    // ---- dtype sniff: int64 (LE) => every odd 32-bit word of seg is 0 ----
    __shared__ int s_is64;
    if (tid < 32) {
        const int* w = (const int*)seg;
        unsigned b = __ballot_sync(0xffffffffu, w[2 * tid + 1] == 0);
        if (tid == 0) s_is64 = (b == 0xffffffffu) ? 1 : 0;
    }
    __syncthreads();
    const int is64 = s_is64;

    // ---- build active-row map with ballots (parallel, no serial scan) ----
    __shared__ unsigned s_masks[MAXROWS / 32];
    __shared__ short    s_rowOf[MAXROWS];   // ordinal -> row
    const int nwords = (N + 31) >> 5;
    {
        int i = tid;
        bool a = false;
        if (i < N) {
            long long lv;
            if (is64) lv = ((const long long*)label)[i];
            else      lv = (long long)((const int*)label)[i];
            a = (lv != 0);
        }
        unsigned b = __ballot_sync(0xffffffffu, a);
        if (i < MAXROWS && (tid & 31) == 0 && (tid >> 5) < nwords)
            s_masks[tid >> 5] = b;
    }
    __syncthreads();

    int cnt = 0;
    #pragma unroll 4
    for (int j = 0; j < nwords; ++j) cnt += __popc(s_masks[j]);

    if (tid < N) {
        int w = tid >> 5, l = tid & 31;
        if ((s_masks[w] >> l) & 1u) {
            int pre = 0;
            for (int j = 0; j < w; ++j) pre += __popc(s_masks[j]);
            pre += __popc(s_masks[w] & ((1u << l) - 1u));
            s_rowOf[pre] = (short)tid;
        }
    }
    __syncthreads();

    // ---- grid-stride over 1024-pixel units ----
    const int totalUnits = cnt * unitsPerRow;
    double acc = 0.0;

    for (int u = blockIdx.x; u < totalUnits; u += gridDim.x) {
        const int q   = u / unitsPerRow;
        const int sub = u - q * unitsPerRow;
        const int row = s_rowOf[q];
        const int p0  = sub * UNIT_PX + tid;
        const float* base = logits + (size_t)row * (size_t)K * (size_t)P;

        if (p0 + 3 * 256 < P) {
            int c[4];
            if (is64) {
                const long long* s = (const long long*)seg + (size_t)row * P;
                #pragma unroll
                for (int i = 0; i < 4; ++i) c[i] = (int)s[p0 + 256 * i];
            } else {
                const int* s = (const int*)seg + (size_t)row * P;
                #pragma unroll
                for (int i = 0; i < 4; ++i) c[i] = s[p0 + 256 * i];
            }
            float l[4];
            #pragma unroll
            for (int i = 0; i < 4; ++i)
                l[i] = __ldg(base + (size_t)c[i] * P + p0 + 256 * i);
            #pragma unroll
            for (int i = 0; i < 4; ++i)
                acc += (double)focal_term(l[i]);
        } else {
            #pragma unroll
            for (int i = 0; i < 4; ++i) {
                int p = p0 + 256 * i;
                if (p >= P) break;
                int cc;
                if (is64) cc = (int)((const long long*)seg)[(size_t)row * P + p];
                else      cc = ((const int*)seg)[(size_t)row * P + p];
                acc += (double)focal_term(__ldg(base + (size_t)cc * P + p));
            }
        }
    }

    // ---- block reduction (double) ----
    for (int off = 16; off > 0; off >>= 1)
        acc += __shfl_down_sync(0xffffffffu, acc, off);
    __shared__ double s_part[8];
    const int lane = tid & 31, wid = tid >> 5;
    if (lane == 0) s_part[wid] = acc;
    __syncthreads();

    __shared__ int s_islast;
    if (tid == 0) {
        double v = 0.0;
        #pragma unroll
        for (int w = 0; w < 8; ++w) v += s_part[w];
        if (v != 0.0) atomicAdd(&g_total, v);
        __threadfence();
        unsigned old = atomicInc(&g_done, gridDim.x - 1u);
        s_islast = (old == gridDim.x - 1u) ? 1 : 0;
    }
    __syncthreads();

    // ---- last block: finalize ----
    if (s_islast) {
        __shared__ float s_loss;
        if (tid == 0) {
            double tot = *((volatile double*)&g_total);
            double c   = (cnt > 0) ? (double)cnt : 1.0;
            s_loss = (float)(-tot / c);
            g_total = 0.0;          // reset for next graph replay
            __threadfence();
        }
        __syncthreads();
        float loss = s_loss;
        for (int i = tid; i < out_size; i += blockDim.x)
            out[i] = (i == 0 || i == 2) ? loss : 0.0f;
    }
}

extern "C" void kernel_launch(void* const* d_in, const int* in_sizes, int n_in,
                              void* d_out, int out_size)
{
    const float* logits = (const float*)d_in[0];
    const void*  seg    = d_in[1];
    const void*  label  = d_in[2];

    int N = in_sizes[2];                 // B*S
    int P = in_sizes[1] / N;             // H*W
    int K = in_sizes[0] / in_sizes[1];   // classes

    const int THREADS = 256;
    int unitsPerRow = (P + UNIT_PX - 1) / UNIT_PX;
    // Launch enough blocks that even at full activity every block gets ~1 unit.
    unsigned int blocks = (unsigned int)N * (unsigned int)unitsPerRow;

    semiloss_fused<<<blocks, THREADS>>>(logits, seg, label,
                                        N, K, P, unitsPerRow,
                                        (float*)d_out, out_size);
}

// round 7
// speedup vs baseline: 1.1576x; 1.0413x over previous
#include <cuda_runtime.h>
#include <cuda_bf16.h>

// SemiLoss focal loss (gamma=6), single fused kernel, flat-indexed.
//   logits : [N, K, P] f32
//   seg    : [N, P]    int64 or int32 (runtime-sniffed)
//   label  : [N]       same int dtype
//   loss = -sum_{n: label[n]!=0} sum_p (1-exp(lp))^6 * lp / count(label!=0)
//   out  = [loss, 0, loss, 0, ...]
//
// Work model: flat pixel index f in [0, cnt*P) over ACTIVE rows only
// (row = rowOf[f / P], p = f % P). Threads grid-stride with batch-4 software
// pipelining: 4 independent seg loads, then 4 gathers, then 4 focal terms.
// Perfect load balance (±1 iteration) for any active-row count, high MLP.
//
// Completion: atomicAdd(g_total) + threadfence + atomicInc(g_done) wrapping
// at gridDim.x (self-resetting); last block finalizes out and resets g_total
// so the kernel is deterministic across CUDA-graph replays.

#define MAXROWS 256
#define BLOCKS  592            // 4 blocks/SM on 148-SM B200
#define THREADS 256

__device__ double       g_total = 0.0;
__device__ unsigned int g_done  = 0u;

__device__ __forceinline__ float focal_term(float lp)
{
    float pt = expf(lp);
    float u  = 1.0f - pt;
    float u2 = u * u;
    return u2 * u2 * u2 * lp;   // positive form; negated at the end
}

__global__ __launch_bounds__(THREADS)
void semiloss_fused(const float* __restrict__ logits,
                    const void*  __restrict__ seg,
                    const void*  __restrict__ label,
                    int N, int K, int P,
                    float* __restrict__ out, int out_size)
{
    const int tid = threadIdx.x;

    // ---- dtype sniff: int64 (LE) => every odd 32-bit word of seg is 0 ----
    __shared__ int s_is64;
    if (tid < 32) {
        const int* w = (const int*)seg;
        unsigned b = __ballot_sync(0xffffffffu, w[2 * tid + 1] == 0);
        if (tid == 0) s_is64 = (b == 0xffffffffu) ? 1 : 0;
    }
    __syncthreads();
    const int is64 = s_is64;

    // ---- build active-row map with ballots ----
    __shared__ unsigned s_masks[MAXROWS / 32];
    __shared__ short    s_rowOf[MAXROWS];   // ordinal -> row
    const int nwords = (N + 31) >> 5;
    {
        bool a = false;
        if (tid < N) {
            long long lv;
            if (is64) lv = ((const long long*)label)[tid];
            else      lv = (long long)((const int*)label)[tid];
            a = (lv != 0);
        }
        unsigned b = __ballot_sync(0xffffffffu, a);
        if ((tid & 31) == 0 && (tid >> 5) < nwords)
            s_masks[tid >> 5] = b;
    }
    __syncthreads();

    int cnt = 0;
    for (int j = 0; j < nwords; ++j) cnt += __popc(s_masks[j]);

    if (tid < N) {
        int w = tid >> 5, l = tid & 31;
        if ((s_masks[w] >> l) & 1u) {
            int pre = 0;
            for (int j = 0; j < w; ++j) pre += __popc(s_masks[j]);
            pre += __popc(s_masks[w] & ((1u << l) - 1u));
            s_rowOf[pre] = (short)tid;
        }
    }
    __syncthreads();

    // ---- flat grid-stride gather-reduce, batch-4 pipelined ----
    const int tot = cnt * P;                         // < 2^31
    const int S   = gridDim.x * blockDim.x;
    int g = blockIdx.x * blockDim.x + tid;

    double acc = 0.0;
    const size_t KP = (size_t)K * (size_t)P;

    for (; g + 3 * S < tot; g += 4 * S) {
        int f[4], row[4], p[4];
        #pragma unroll
        for (int i = 0; i < 4; ++i) {
            f[i]   = g + i * S;
            int q  = f[i] / P;
            p[i]   = f[i] - q * P;
            row[i] = s_rowOf[q];
        }
        // batch seg loads (independent)
        int c[4];
        if (is64) {
            const long long* sp = (const long long*)seg;
            #pragma unroll
            for (int i = 0; i < 4; ++i)
                c[i] = (int)__ldg(sp + (size_t)row[i] * P + p[i]);
        } else {
            const int* sp = (const int*)seg;
            #pragma unroll
            for (int i = 0; i < 4; ++i)
                c[i] = __ldg(sp + (size_t)row[i] * P + p[i]);
        }
        // batch gathers (independent)
        float l[4];
        #pragma unroll
        for (int i = 0; i < 4; ++i)
            l[i] = __ldg(logits + (size_t)row[i] * KP + (size_t)c[i] * P + p[i]);
        #pragma unroll
        for (int i = 0; i < 4; ++i)
            acc += (double)focal_term(l[i]);
    }
    for (; g < tot; g += S) {
        int q = g / P;
        int p = g - q * P;
        int row = s_rowOf[q];
        int c;
        if (is64) c = (int)__ldg((const long long*)seg + (size_t)row * P + p);
        else      c = __ldg((const int*)seg + (size_t)row * P + p);
        acc += (double)focal_term(
            __ldg(logits + (size_t)row * KP + (size_t)c * P + p));
    }

    // ---- block reduction (double) ----
    for (int off = 16; off > 0; off >>= 1)
        acc += __shfl_down_sync(0xffffffffu, acc, off);
    __shared__ double s_part[8];
    const int lane = tid & 31, wid = tid >> 5;
    if (lane == 0) s_part[wid] = acc;
    __syncthreads();

    __shared__ int s_islast;
    if (tid == 0) {
        double v = 0.0;
        #pragma unroll
        for (int w = 0; w < 8; ++w) v += s_part[w];
        if (v != 0.0) atomicAdd(&g_total, v);
        __threadfence();
        unsigned old = atomicInc(&g_done, gridDim.x - 1u);
        s_islast = (old == gridDim.x - 1u) ? 1 : 0;
    }
    __syncthreads();

    // ---- last block: finalize ----
    if (s_islast) {
        __shared__ float s_loss;
        if (tid == 0) {
            double tot_d = *((volatile double*)&g_total);
            double c     = (cnt > 0) ? (double)cnt : 1.0;
            s_loss = (float)(-tot_d / c);
            g_total = 0.0;          // reset for next graph replay
            __threadfence();
        }
        __syncthreads();
        float loss = s_loss;
        for (int i = tid; i < out_size; i += blockDim.x)
            out[i] = (i == 0 || i == 2) ? loss : 0.0f;
    }
}

extern "C" void kernel_launch(void* const* d_in, const int* in_sizes, int n_in,
                              void* d_out, int out_size)
{
    const float* logits = (const float*)d_in[0];
    const void*  seg    = d_in[1];
    const void*  label  = d_in[2];

    int N = in_sizes[2];                 // B*S
    int P = in_sizes[1] / N;             // H*W
    int K = in_sizes[0] / in_sizes[1];   // classes

    semiloss_fused<<<BLOCKS, THREADS>>>(logits, seg, label,
                                        N, K, P,
                                        (float*)d_out, out_size);
}